// round 16
// baseline (speedup 1.0000x reference)
#include <cuda_runtime.h>
#include <cuda_bf16.h>
#include <cuda_fp16.h>
#include <math.h>
#include <stdint.h>

#define SEQ    2048
#define BATCH  2
#define TOK    4096
#define DIM    1024
#define NHEAD  16
#define KVHEAD 4
#define HDIM   64
#define NLAYER 8
#define FF     4096
#define VOCAB  32000

typedef __nv_bfloat16 bf16;

// ---------------- scratch ----------------
__device__ float g_h   [TOK * DIM];
__device__ float g_qkv [TOK * 1536];          // [q(1024)|k(256)|v(256)]
__device__ float g_f13 [TOK * 8192];          // [f1(4096)|f3(4096)]
__device__ float g_cos [SEQ * 32];
__device__ float g_sin [SEQ * 32];
// bf16 3K expanded activations (A: [hi|hi|lo])
__device__ bf16 g_xne [TOK * 3072];
__device__ bf16 g_atte[TOK * 3072];
// fp16 2K expanded activations (A: [hi|lo])
__device__ __half g_xnh [TOK * 2048];
__device__ __half g_f1h [(size_t)TOK * 8192];
// bf16 3K expanded weights (B: [hi|lo|hi])
__device__ bf16 e_wqkv[(size_t)NLAYER * 1536 * 3072];
__device__ bf16 e_wo  [(size_t)NLAYER * 1024 * 3072];
// fp16 2K expanded weights (B: [hi|hi])
__device__ __half e_w13h[(size_t)NLAYER * 8192 * 2048];
__device__ __half e_w2h [(size_t)NLAYER * 1024 * 8192];
__device__ __half e_embh[(size_t)VOCAB * 2048];

__device__ __forceinline__ void split2(float x, bf16& hi, bf16& lo) {
    hi = __float2bfloat16_rn(x);
    lo = __float2bfloat16_rn(x - __bfloat162float(hi));
}
__device__ __forceinline__ void split2h(float x, __half& hi, __half& lo) {
    hi = __float2half_rn(x);
    lo = __float2half_rn(x - __half2float(hi));
}

// ---- packed f32x2 helpers (sm_103 Blackwell packed math, PTX-only) ----
#define F32X2_FMA(acc, a, b) \
    asm volatile("fma.rn.f32x2 %0, %1, %2, %0;" : "+l"(acc) : "l"(a), "l"(b))
#define F32X2_MUL(d, a, b) \
    asm volatile("mul.rn.f32x2 %0, %1, %2;" : "=l"(d) : "l"(a), "l"(b))
#define F32X2_ADD(d, a, b) \
    asm volatile("add.rn.f32x2 %0, %1, %2;" : "=l"(d) : "l"(a), "l"(b))
#define PACK2(d, lo, hi) \
    asm("mov.b64 %0, {%1, %2};" : "=l"(d) : "f"(lo), "f"(hi))
#define UNPACK2(lo, hi, d) \
    asm("mov.b64 {%0, %1}, %2;" : "=f"(lo), "=f"(hi) : "l"(d))
#define LDS_V2U64(a, b, addr) \
    asm volatile("ld.shared.v2.u64 {%0, %1}, [%2];" : "=l"(a), "=l"(b) : "r"(addr))

// ------- bf16 weight expansion, 8 elems/thread: rows = [hi | lo | hi] -------
__global__ void expand_w_kernel(const float* __restrict__ in, bf16* __restrict__ out,
                                int K, int rows_pl, size_t lstride, int row_off) {
    size_t idx = ((size_t)blockIdx.x * 256 + threadIdx.x) * 8;
    size_t rt = idx / K;
    int k  = (int)(idx % K);
    int l  = (int)(rt / rows_pl);
    int r  = (int)(rt % rows_pl);
    float4 x0 = *(const float4*)(in + idx);
    float4 x1 = *(const float4*)(in + idx + 4);
    float xs[8] = {x0.x, x0.y, x0.z, x0.w, x1.x, x1.y, x1.z, x1.w};
    bf16 hi[8], lo[8];
    #pragma unroll
    for (int i = 0; i < 8; i++) split2(xs[i], hi[i], lo[i]);
    bf16* o = out + (size_t)l * lstride + (size_t)(row_off + r) * (3 * K);
    *(uint4*)(o + k)         = *(uint4*)hi;
    *(uint4*)(o + K + k)     = *(uint4*)lo;
    *(uint4*)(o + 2 * K + k) = *(uint4*)hi;
}

// ------- fp16 weight expansion, 8 elems/thread: rows = [hi | hi] (2K) -------
__global__ void expand_w_f16_kernel(const float* __restrict__ in, __half* __restrict__ out,
                                    int K, int rows_pl, size_t lstride, int row_off) {
    size_t idx = ((size_t)blockIdx.x * 256 + threadIdx.x) * 8;
    size_t rt = idx / K;
    int k  = (int)(idx % K);
    int l  = (int)(rt / rows_pl);
    int r  = (int)(rt % rows_pl);
    float4 x0 = *(const float4*)(in + idx);
    float4 x1 = *(const float4*)(in + idx + 4);
    float xs[8] = {x0.x, x0.y, x0.z, x0.w, x1.x, x1.y, x1.z, x1.w};
    __half hi[8];
    #pragma unroll
    for (int i = 0; i < 8; i++) hi[i] = __float2half_rn(xs[i]);
    __half* o = out + (size_t)l * lstride + (size_t)(row_off + r) * (2 * K);
    *(uint4*)(o + k)     = *(uint4*)hi;
    *(uint4*)(o + K + k) = *(uint4*)hi;
}

// ---------------- RoPE tables ----------------
__global__ void rope_init_kernel() {
    int t = blockIdx.x, j = threadIdx.x;
    double inv   = pow(10000.0, -(2.0 * j) / 64.0);
    double r     = 81920.0 * inv / (2.0 * M_PI);
    double gamma = (r - 1.0) / 31.0;
    gamma = gamma < 0.0 ? 0.0 : (gamma > 1.0 ? 1.0 : gamma);
    double inv2  = inv * ((1.0 - gamma) / 40.0 + gamma);
    double c     = sqrt(0.1 * log(40.0) + 1.0);
    double ang   = (double)t * inv2 / c;
    g_cos[t * 32 + j] = (float)cos(ang);
    g_sin[t * 32 + j] = (float)sin(ang);
}

__global__ void embed_kernel(const int* __restrict__ ids, const float* __restrict__ emb) {
    int t = blockIdx.x;
    const float* src = emb + (size_t)ids[t] * DIM;
    float* dst = g_h + (size_t)t * DIM;
    for (int d = threadIdx.x; d < DIM; d += blockDim.x) dst[d] = src[d];
}

// ---------------- shared rmsnorm prologue ----------------
__device__ __forceinline__ float rms_scale(const float* xr, int tid) {
    float s = 0.f;
    #pragma unroll
    for (int i = 0; i < 4; i++) { float v = xr[tid + i * 256]; s += v * v; }
    #pragma unroll
    for (int off = 16; off; off >>= 1) s += __shfl_xor_sync(0xffffffffu, s, off);
    __shared__ float red[8]; __shared__ float rsv;
    if ((tid & 31) == 0) red[tid >> 5] = s;
    __syncthreads();
    if (tid == 0) {
        float t = 0.f;
        #pragma unroll
        for (int i = 0; i < 8; i++) t += red[i];
        rsv = rsqrtf(t / (float)DIM + 1e-6f);
    }
    __syncthreads();
    return rsv;
}

// ---------------- rmsnorm -> bf16 3K [hi|hi|lo] ----------------
__global__ __launch_bounds__(256) void rmsnorm_expand_kernel(
    const float* __restrict__ x, const float* __restrict__ w, bf16* __restrict__ o) {
    int row = blockIdx.x, tid = threadIdx.x;
    const float* xr = x + (size_t)row * DIM;
    float rs = rms_scale(xr, tid);
    bf16* orow = o + (size_t)row * 3072;
    #pragma unroll
    for (int i = 0; i < 2; i++) {
        int d = 2 * (tid + i * 256);
        float2 xv = *(const float2*)(xr + d);
        float2 wv = *(const float2*)(w + d);
        float y0 = xv.x * rs * wv.x, y1 = xv.y * rs * wv.y;
        bf16 h0, l0, h1, l1;
        split2(y0, h0, l0); split2(y1, h1, l1);
        *(__nv_bfloat162*)(orow + d)        = __nv_bfloat162(h0, h1);
        *(__nv_bfloat162*)(orow + 1024 + d) = __nv_bfloat162(h0, h1);
        *(__nv_bfloat162*)(orow + 2048 + d) = __nv_bfloat162(l0, l1);
    }
}

// ---------------- rmsnorm -> fp16 2K [hi|lo] ----------------
__global__ __launch_bounds__(256) void rmsnorm_expand_f16_kernel(
    const float* __restrict__ x, const float* __restrict__ w, __half* __restrict__ o) {
    int row = blockIdx.x, tid = threadIdx.x;
    const float* xr = x + (size_t)row * DIM;
    float rs = rms_scale(xr, tid);
    __half* orow = o + (size_t)row * 2048;
    #pragma unroll
    for (int i = 0; i < 2; i++) {
        int d = 2 * (tid + i * 256);
        float2 xv = *(const float2*)(xr + d);
        float2 wv = *(const float2*)(w + d);
        float y0 = xv.x * rs * wv.x, y1 = xv.y * rs * wv.y;
        __half h0, l0, h1, l1;
        split2h(y0, h0, l0); split2h(y1, h1, l1);
        *(__half2*)(orow + d)        = __half2(h0, h1);
        *(__half2*)(orow + 1024 + d) = __half2(l0, l1);
    }
}

// ================= b16 tensor-core GEMM (BK=64, bf16 or fp16) =================
#define BM 128
#define BN 256
#define BKE 64
#define A_BYTES (BM * BKE * 2)             // 16384
#define B_BYTES (BN * BKE * 2)             // 32768
#define STAGE_BYTES (A_BYTES + B_BYTES)    // 49152
#define SMEM_DYN (2 * STAGE_BYTES)         // 98304

#define CP_ASYNC16(dst, src) \
    asm volatile("cp.async.cg.shared.global [%0], [%1], 16;" :: "r"(dst), "l"(src))
#define CP_COMMIT()  asm volatile("cp.async.commit_group;")
#define CP_WAIT1()   asm volatile("cp.async.wait_group 1;")
#define LDSM_X4(r0, r1, r2, r3, addr) \
    asm volatile("ldmatrix.sync.aligned.m8n8.x4.shared.b16 {%0,%1,%2,%3}, [%4];" \
        : "=r"(r0), "=r"(r1), "=r"(r2), "=r"(r3) : "r"(addr))

template <int FP16>
__device__ __forceinline__ void MMA16(float* c, uint32_t a0, uint32_t a1,
                                      uint32_t a2, uint32_t a3,
                                      uint32_t b0, uint32_t b1) {
    if constexpr (FP16)
        asm volatile("mma.sync.aligned.m16n8k16.row.col.f32.f16.f16.f32 "
            "{%0,%1,%2,%3}, {%4,%5,%6,%7}, {%8,%9}, {%0,%1,%2,%3};"
            : "+f"(c[0]), "+f"(c[1]), "+f"(c[2]), "+f"(c[3])
            : "r"(a0), "r"(a1), "r"(a2), "r"(a3), "r"(b0), "r"(b1));
    else
        asm volatile("mma.sync.aligned.m16n8k16.row.col.f32.bf16.bf16.f32 "
            "{%0,%1,%2,%3}, {%4,%5,%6,%7}, {%8,%9}, {%0,%1,%2,%3};"
            : "+f"(c[0]), "+f"(c[1]), "+f"(c[2]), "+f"(c[3])
            : "r"(a0), "r"(a1), "r"(a2), "r"(a3), "r"(b0), "r"(b1));
}

template <int RES, int FP16>
__global__ __launch_bounds__(256) void gemm_b16(
    const uint16_t* __restrict__ A, const uint16_t* __restrict__ W,
    const float* __restrict__ R, float* __restrict__ C, int N, int K) {
    extern __shared__ __align__(16) char smem[];
    const int tid  = threadIdx.x;
    const int lane = tid & 31;
    const int wid  = tid >> 5;
    const int wm   = wid >> 2;
    const int wn   = wid & 3;
    const int bm   = blockIdx.y * BM;
    const int bn   = blockIdx.x * BN;
    const uint32_t smem_u = (uint32_t)__cvta_generic_to_shared(smem);

    const int lrow = tid >> 3;
    const int lcol = tid & 7;
    const uint16_t* AgBase = A + (size_t)bm * K;
    const uint16_t* WgBase = W + (size_t)bn * K;

    const int flr = lane & 15;
    const int fhi = lane >> 4;
    int aRow[4], aXor[4];
    #pragma unroll
    for (int i = 0; i < 4; i++) { aRow[i] = wm * 64 + i * 16 + flr; aXor[i] = aRow[i] & 7; }
    const int bkf = (lane >> 3) & 1;
    int bRow[4], bXor[4];
    #pragma unroll
    for (int p = 0; p < 4; p++) {
        bRow[p] = wn * 64 + (lane & 7) + fhi * 8 + p * 16;
        bXor[p] = bRow[p] & 7;
    }

    float acc[4][8][4];
    #pragma unroll
    for (int i = 0; i < 4; i++)
        #pragma unroll
        for (int j = 0; j < 8; j++)
            #pragma unroll
            for (int q = 0; q < 4; q++) acc[i][j][q] = 0.f;

    const int nk = K / BKE;

    auto load_stage = [&](int kt) {
        uint32_t base = smem_u + (kt & 1) * STAGE_BYTES;
        int k0 = kt * BKE;
        #pragma unroll
        for (int it = 0; it < 4; it++) {
            int r = lrow + it * 32;
            uint32_t dst = base + r * 128 + ((lcol ^ (r & 7)) << 4);
            CP_ASYNC16(dst, AgBase + (size_t)r * K + k0 + lcol * 8);
        }
        uint32_t bb = base + A_BYTES;
        #pragma unroll
        for (int it = 0; it < 8; it++) {
            int r = lrow + it * 32;
            uint32_t dst = bb + r * 128 + ((lcol ^ (r & 7)) << 4);
            CP_ASYNC16(dst, WgBase + (size_t)r * K + k0 + lcol * 8);
        }
    };

    load_stage(0);
    CP_COMMIT();

    for (int kt = 0; kt < nk; kt++) {
        if (kt + 1 < nk) load_stage(kt + 1);
        CP_COMMIT();
        CP_WAIT1();
        __syncthreads();

        uint32_t cbase = smem_u + (kt & 1) * STAGE_BYTES;
        #pragma unroll
        for (int s = 0; s < 4; s++) {
            uint32_t af[4][4];
            #pragma unroll
            for (int i = 0; i < 4; i++) {
                uint32_t addr = cbase + aRow[i] * 128 + (((2 * s + fhi) ^ aXor[i]) << 4);
                LDSM_X4(af[i][0], af[i][1], af[i][2], af[i][3], addr);
            }
            #pragma unroll
            for (int p = 0; p < 4; p++) {
                uint32_t addr = cbase + (uint32_t)A_BYTES + bRow[p] * 128 +
                                (((2 * s + bkf) ^ bXor[p]) << 4);
                uint32_t b0, b1, b2, b3;
                LDSM_X4(b0, b1, b2, b3, addr);
                #pragma unroll
                for (int i = 0; i < 4; i++) {
                    MMA16<FP16>(acc[i][2 * p],     af[i][0], af[i][1], af[i][2], af[i][3], b0, b1);
                    MMA16<FP16>(acc[i][2 * p + 1], af[i][0], af[i][1], af[i][2], af[i][3], b2, b3);
                }
            }
        }
        __syncthreads();
    }

    const int gid = lane >> 2, tig = lane & 3;
    #pragma unroll
    for (int i = 0; i < 4; i++) {
        int r0 = bm + wm * 64 + i * 16 + gid;
        #pragma unroll
        for (int j = 0; j < 8; j++) {
            int c0 = bn + wn * 64 + j * 8 + tig * 2;
            size_t o0 = (size_t)r0 * N + c0;
            size_t o1 = o0 + (size_t)8 * N;
            float2 v0 = make_float2(acc[i][j][0], acc[i][j][1]);
            float2 v1 = make_float2(acc[i][j][2], acc[i][j][3]);
            if (RES) {
                float2 ra = *(const float2*)(R + o0);
                float2 rb = *(const float2*)(R + o1);
                v0.x += ra.x; v0.y += ra.y; v1.x += rb.x; v1.y += rb.y;
            }
            *(float2*)(C + o0) = v0;
            *(float2*)(C + o1) = v1;
        }
    }
}

// ---------------- RoPE on qkv slab ----------------
__global__ void rope_kernel(float* __restrict__ x, int nheads, int off) {
    int idx = blockIdx.x * 256 + threadIdx.x;
    int i  = idx & 31;
    int hh = (idx >> 5) % nheads;
    int t  = idx / (32 * nheads);
    int s  = t & (SEQ - 1);
    float c  = g_cos[s * 32 + i];
    float sn = g_sin[s * 32 + i];
    float* p = x + (size_t)t * 1536 + off + hh * HDIM;
    float x1 = p[i], x2 = p[i + 32];
    p[i]      = x1 * c - x2 * sn;
    p[i + 32] = x2 * c + x1 * sn;
}

// ------- causal GQA flash attention: split-query f32x2 (256 thr = 128q x 2 halves) -------
// Thread owns half a query row (32 dims). Partner = tid^1 (same warp).
// Partial scores exchanged through Ss smem; full score recomputed by both
// halves (reads only after syncwarp -> no overwrite hazard). 96KB dyn smem:
// K(16K) | V(16K) | Ss[64][256](64K). 2 blocks/SM -> 16 warps/SM.
#define ATTN_SMEM (16384 + 16384 + 64 * 256 * 4)   // 98304
__global__ __launch_bounds__(256) void attn_kernel(
    const float* __restrict__ qkv, bf16* __restrict__ oe) {
    extern __shared__ __align__(16) char asmem[];
    float* KsF = (float*)asmem;
    float* VsF = (float*)(asmem + 16384);
    float* Ss  = (float*)(asmem + 32768);
    const uint32_t ksb = (uint32_t)__cvta_generic_to_shared(asmem);
    const uint32_t vsb = ksb + 16384;

    int qt = blockIdx.x, h = blockIdx.y, b = blockIdx.z;
    int g = h >> 2;
    int tid  = threadIdx.x;
    int half = tid & 1;
    int ql   = tid >> 1;               // 0..127
    int qi   = qt * 128 + ql;

    // load own half of q (scaled), packed
    const float* qp = qkv + (size_t)(b * SEQ + qi) * 1536 + h * HDIM + half * 32;
    uint64_t q2[16];
    #pragma unroll
    for (int d = 0; d < 32; d += 4) {
        float4 t4 = *(const float4*)(qp + d);
        PACK2(q2[d / 2],     t4.x * 0.125f, t4.y * 0.125f);
        PACK2(q2[d / 2 + 1], t4.z * 0.125f, t4.w * 0.125f);
    }
    float m = -1e30f, l = 0.f;
    uint64_t acc2[16];
    #pragma unroll
    for (int i = 0; i < 16; i++) acc2[i] = 0ull;

    const int jmax = (qt * 128 + 127) >> 6;
    for (int j = 0; j <= jmax; j++) {
        const float* kp = qkv + (size_t)(b * SEQ + j * 64) * 1536 + 1024 + g * HDIM;
        const float* vp = kp + 256;
        __syncthreads();
        #pragma unroll
        for (int i = 0; i < 4; i++) {               // 64x64 K and V tiles
            int idx = i * 256 + tid;                // 0..1023 float4 slots
            int r = idx >> 4, c = (idx & 15) * 4;
            *(float4*)(KsF + r * 64 + c) = *(const float4*)(kp + (size_t)r * 1536 + c);
            *(float4*)(VsF + r * 64 + c) = *(const float4*)(vp + (size_t)r * 1536 + c);
        }
        __syncthreads();

        // ---- partial scores over own 32 dims ----
        #pragma unroll
        for (int kk = 0; kk < 64; kk++) {
            uint64_t s01 = 0ull, s23 = 0ull;
            uint32_t ka = ksb + kk * 256 + half * 128;
            #pragma unroll
            for (int d = 0; d < 32; d += 4) {
                uint64_t k01, k23;
                LDS_V2U64(k01, k23, ka + d * 4);
                F32X2_FMA(s01, q2[d / 2], k01);
                F32X2_FMA(s23, q2[d / 2 + 1], k23);
            }
            uint64_t st;
            F32X2_ADD(st, s01, s23);
            float f0, f1;
            UNPACK2(f0, f1, st);
            Ss[kk * 256 + tid] = f0 + f1;
        }
        __syncwarp();                                // partner is in same warp

        // ---- combine + running max ----
        float tmax = -1e30f;
        #pragma unroll
        for (int kk = 0; kk < 64; kk++) {
            float full = Ss[kk * 256 + tid] + Ss[kk * 256 + (tid ^ 1)];
            full = (j * 64 + kk <= qi) ? full : -1e30f;
            tmax = fmaxf(tmax, full);
        }
        float nm = fmaxf(m, tmax);
        float corr = __expf(m - nm);
        l *= corr;
        uint64_t cc;
        PACK2(cc, corr, corr);
        #pragma unroll
        for (int i = 0; i < 16; i++) F32X2_MUL(acc2[i], acc2[i], cc);

        // ---- P·V on own 32 dims ----
        #pragma unroll
        for (int kk = 0; kk < 64; kk++) {
            float full = Ss[kk * 256 + tid] + Ss[kk * 256 + (tid ^ 1)];
            full = (j * 64 + kk <= qi) ? full : -1e30f;
            float p = __expf(full - nm);
            l += p;
            uint64_t pp;
            PACK2(pp, p, p);
            uint32_t va = vsb + kk * 256 + half * 128;
            #pragma unroll
            for (int d = 0; d < 32; d += 4) {
                uint64_t v01, v23;
                LDS_V2U64(v01, v23, va + d * 4);
                F32X2_FMA(acc2[d / 2], pp, v01);
                F32X2_FMA(acc2[d / 2 + 1], pp, v23);
            }
        }
        m = nm;
    }

    float inv = 1.f / l;
    bf16* op = oe + (size_t)(b * SEQ + qi) * 3072 + h * HDIM + half * 32;
    #pragma unroll
    for (int d = 0; d < 32; d += 2) {
        float a0, a1;
        UNPACK2(a0, a1, acc2[d / 2]);
        float y0 = a0 * inv, y1 = a1 * inv;
        bf16 h0, l0, h1, l1;
        split2(y0, h0, l0); split2(y1, h1, l1);
        *(__nv_bfloat162*)(op + d)        = __nv_bfloat162(h0, h1);
        *(__nv_bfloat162*)(op + 1024 + d) = __nv_bfloat162(h0, h1);
        *(__nv_bfloat162*)(op + 2048 + d) = __nv_bfloat162(l0, l1);
    }
}

// ---------------- SwiGLU -> fp16 2K [hi|lo], 4 elems/thread ----------------
__global__ void swiglu_expand_f16_kernel() {
    int i4 = (blockIdx.x * 256 + threadIdx.x) * 4;   // over TOK*FF
    int t = i4 >> 12, c = i4 & 4095;
    float4 a4 = *(const float4*)(g_f13 + (size_t)t * 8192 + c);
    float4 b4 = *(const float4*)(g_f13 + (size_t)t * 8192 + 4096 + c);
    float as[4] = {a4.x, a4.y, a4.z, a4.w};
    float bs[4] = {b4.x, b4.y, b4.z, b4.w};
    __half hi[4], lo[4];
    #pragma unroll
    for (int i = 0; i < 4; i++) {
        float u = (as[i] / (1.f + __expf(-as[i]))) * bs[i];
        split2h(u, hi[i], lo[i]);
    }
    __half* o = g_f1h + (size_t)t * 8192;
    *(uint2*)(o + c)        = *(uint2*)hi;
    *(uint2*)(o + 4096 + c) = *(uint2*)lo;
}

// ---------------- host orchestration ----------------
extern "C" void kernel_launch(void* const* d_in, const int* in_sizes, int n_in,
                              void* d_out, int out_size) {
    const int*   ids = (const int*)d_in[0];
    const float* emb = (const float*)d_in[1];
    const float* wq  = (const float*)d_in[2];
    const float* wk  = (const float*)d_in[3];
    const float* wv  = (const float*)d_in[4];
    const float* wo  = (const float*)d_in[5];
    const float* n1  = (const float*)d_in[6];
    const float* n2  = (const float*)d_in[7];
    const float* w1  = (const float*)d_in[8];
    const float* w2  = (const float*)d_in[9];
    const float* w3  = (const float*)d_in[10];
    const float* fnw = (const float*)d_in[11];
    float* out = (float*)d_out;

    static int smem_set = 0;
    if (!smem_set) {
        cudaFuncSetAttribute(gemm_b16<0,0>, cudaFuncAttributeMaxDynamicSharedMemorySize, SMEM_DYN);
        cudaFuncSetAttribute(gemm_b16<1,0>, cudaFuncAttributeMaxDynamicSharedMemorySize, SMEM_DYN);
        cudaFuncSetAttribute(gemm_b16<0,1>, cudaFuncAttributeMaxDynamicSharedMemorySize, SMEM_DYN);
        cudaFuncSetAttribute(gemm_b16<1,1>, cudaFuncAttributeMaxDynamicSharedMemorySize, SMEM_DYN);
        cudaFuncSetAttribute(attn_kernel,   cudaFuncAttributeMaxDynamicSharedMemorySize, ATTN_SMEM);
        smem_set = 1;
    }

    float *h, *qkv, *f13;
    bf16 *xne, *atte, *ewqkv, *ewo;
    __half *xnh, *f1h, *ew13h, *ew2h, *eembh;
    cudaGetSymbolAddress((void**)&h,     g_h);
    cudaGetSymbolAddress((void**)&qkv,   g_qkv);
    cudaGetSymbolAddress((void**)&f13,   g_f13);
    cudaGetSymbolAddress((void**)&xne,   g_xne);
    cudaGetSymbolAddress((void**)&atte,  g_atte);
    cudaGetSymbolAddress((void**)&xnh,   g_xnh);
    cudaGetSymbolAddress((void**)&f1h,   g_f1h);
    cudaGetSymbolAddress((void**)&ewqkv, e_wqkv);
    cudaGetSymbolAddress((void**)&ewo,   e_wo);
    cudaGetSymbolAddress((void**)&ew13h, e_w13h);
    cudaGetSymbolAddress((void**)&ew2h,  e_w2h);
    cudaGetSymbolAddress((void**)&eembh, e_embh);

    // ---- expand weights: bf16 3K for qkv/wo, fp16 2K for w13/w2/emb ----
    expand_w_kernel<<<(NLAYER * 1024 * 1024) / 2048, 256>>>(wq, ewqkv, 1024, 1024, (size_t)1536 * 3072, 0);
    expand_w_kernel<<<(NLAYER * 256  * 1024) / 2048, 256>>>(wk, ewqkv, 1024, 256,  (size_t)1536 * 3072, 1024);
    expand_w_kernel<<<(NLAYER * 256  * 1024) / 2048, 256>>>(wv, ewqkv, 1024, 256,  (size_t)1536 * 3072, 1280);
    expand_w_kernel<<<(NLAYER * 1024 * 1024) / 2048, 256>>>(wo, ewo,   1024, 1024, (size_t)1024 * 3072, 0);
    expand_w_f16_kernel<<<(NLAYER * 4096 * 1024) / 2048, 256>>>(w1, ew13h, 1024, 4096, (size_t)8192 * 2048, 0);
    expand_w_f16_kernel<<<(NLAYER * 4096 * 1024) / 2048, 256>>>(w3, ew13h, 1024, 4096, (size_t)8192 * 2048, 4096);
    expand_w_f16_kernel<<<(NLAYER * 1024 * 4096) / 2048, 256>>>(w2, ew2h,  4096, 1024, (size_t)1024 * 8192, 0);
    expand_w_f16_kernel<<<(VOCAB * 1024) / 2048, 256>>>(emb, eembh, 1024, VOCAB, 0, 0);

    rope_init_kernel<<<SEQ, 32>>>();
    embed_kernel<<<TOK, 256>>>(ids, emb);

    for (int l = 0; l < NLAYER; l++) {
        // --- attention block: bf16 3K (proven path) ---
        rmsnorm_expand_kernel<<<TOK, 256>>>(h, n1 + (size_t)l * DIM, xne);
        gemm_b16<0,0><<<dim3(1536 / BN, TOK / BM), 256, SMEM_DYN>>>(
            (const uint16_t*)xne, (const uint16_t*)(ewqkv + (size_t)l * 1536 * 3072),
            nullptr, qkv, 1536, 3072);
        rope_kernel<<<(TOK * NHEAD * 32) / 256, 256>>>(qkv, NHEAD, 0);
        rope_kernel<<<(TOK * KVHEAD * 32) / 256, 256>>>(qkv, KVHEAD, 1024);
        attn_kernel<<<dim3(SEQ / 128, NHEAD, BATCH), 256, ATTN_SMEM>>>(qkv, atte);
        gemm_b16<1,0><<<dim3(1024 / BN, TOK / BM), 256, SMEM_DYN>>>(
            (const uint16_t*)atte, (const uint16_t*)(ewo + (size_t)l * 1024 * 3072),
            h, h, 1024, 3072);
        // --- FFN block: fp16 2K ---
        rmsnorm_expand_f16_kernel<<<TOK, 256>>>(h, n2 + (size_t)l * DIM, xnh);
        gemm_b16<0,1><<<dim3(8192 / BN, TOK / BM), 256, SMEM_DYN>>>(
            (const uint16_t*)xnh, (const uint16_t*)(ew13h + (size_t)l * 8192 * 2048),
            nullptr, f13, 8192, 2048);
        swiglu_expand_f16_kernel<<<(TOK * FF) / 1024, 256>>>();
        gemm_b16<1,1><<<dim3(1024 / BN, TOK / BM), 256, SMEM_DYN>>>(
            (const uint16_t*)f1h, (const uint16_t*)(ew2h + (size_t)l * 1024 * 8192),
            h, h, 1024, 8192);
    }
    // --- logits: fp16 2K ---
    rmsnorm_expand_f16_kernel<<<TOK, 256>>>(h, fnw, xnh);
    gemm_b16<0,1><<<dim3(VOCAB / BN, TOK / BM), 256, SMEM_DYN>>>(
        (const uint16_t*)xnh, (const uint16_t*)eembh, nullptr, out, VOCAB, 2048);
}

// round 17
// speedup vs baseline: 1.9688x; 1.9688x over previous
#include <cuda_runtime.h>
#include <cuda_bf16.h>
#include <cuda_fp16.h>
#include <math.h>
#include <stdint.h>

#define SEQ    2048
#define BATCH  2
#define TOK    4096
#define DIM    1024
#define NHEAD  16
#define KVHEAD 4
#define HDIM   64
#define NLAYER 8
#define FF     4096
#define VOCAB  32000

typedef __nv_bfloat16 bf16;

__device__ float g_h   [TOK * DIM];
__device__ float g_qkv [TOK * 1536];
__device__ float g_f13 [TOK * 8192];
__device__ float g_cos [SEQ * 32];
__device__ float g_sin [SEQ * 32];
__device__ bf16 g_xne [TOK * 3072];
__device__ bf16 g_atte[TOK * 3072];
__device__ __half g_xnh [TOK * 2048];
__device__ __half g_f1h [(size_t)TOK * 8192];
__device__ bf16 e_wqkv[(size_t)NLAYER * 1536 * 3072];
__device__ bf16 e_wo  [(size_t)NLAYER * 1024 * 3072];
__device__ __half e_w13h[(size_t)NLAYER * 8192 * 2048];
__device__ __half e_w2h [(size_t)NLAYER * 1024 * 8192];
__device__ __half e_embh[(size_t)VOCAB * 2048];
// attention operands (per layer, post-rope)
__device__ bf16 g_qhi [(size_t)BATCH * NHEAD  * SEQ * 64];
__device__ bf16 g_qlo [(size_t)BATCH * NHEAD  * SEQ * 64];
__device__ bf16 g_khi [(size_t)BATCH * KVHEAD * SEQ * 64];
__device__ bf16 g_klo [(size_t)BATCH * KVHEAD * SEQ * 64];
__device__ bf16 g_vthi[(size_t)BATCH * KVHEAD * SEQ * 64];
__device__ bf16 g_vtlo[(size_t)BATCH * KVHEAD * SEQ * 64];

__device__ __forceinline__ void split2(float x, bf16& hi, bf16& lo) {
    hi = __float2bfloat16_rn(x);
    lo = __float2bfloat16_rn(x - __bfloat162float(hi));
}
__device__ __forceinline__ void split2h(float x, __half& hi, __half& lo) {
    hi = __float2half_rn(x);
    lo = __float2half_rn(x - __half2float(hi));
}
__device__ __forceinline__ uint32_t pack_bf2(bf16 a, bf16 b) {
    __nv_bfloat162 t(a, b);
    return *reinterpret_cast<uint32_t*>(&t);
}

__global__ void expand_w_kernel(const float* __restrict__ in, bf16* __restrict__ out,
                                int K, int rows_pl, size_t lstride, int row_off) {
    size_t idx = ((size_t)blockIdx.x * 256 + threadIdx.x) * 8;
    size_t rt = idx / K;
    int k = (int)(idx % K), l = (int)(rt / rows_pl), r = (int)(rt % rows_pl);
    float4 x0 = *(const float4*)(in + idx);
    float4 x1 = *(const float4*)(in + idx + 4);
    float xs[8] = {x0.x, x0.y, x0.z, x0.w, x1.x, x1.y, x1.z, x1.w};
    bf16 hi[8], lo[8];
    #pragma unroll
    for (int i = 0; i < 8; i++) split2(xs[i], hi[i], lo[i]);
    bf16* o = out + (size_t)l * lstride + (size_t)(row_off + r) * (3 * K);
    *(uint4*)(o + k)         = *(uint4*)hi;
    *(uint4*)(o + K + k)     = *(uint4*)lo;
    *(uint4*)(o + 2 * K + k) = *(uint4*)hi;
}

__global__ void expand_w_f16_kernel(const float* __restrict__ in, __half* __restrict__ out,
                                    int K, int rows_pl, size_t lstride, int row_off) {
    size_t idx = ((size_t)blockIdx.x * 256 + threadIdx.x) * 8;
    size_t rt = idx / K;
    int k = (int)(idx % K), l = (int)(rt / rows_pl), r = (int)(rt % rows_pl);
    float4 x0 = *(const float4*)(in + idx);
    float4 x1 = *(const float4*)(in + idx + 4);
    float xs[8] = {x0.x, x0.y, x0.z, x0.w, x1.x, x1.y, x1.z, x1.w};
    __half hi[8];
    #pragma unroll
    for (int i = 0; i < 8; i++) hi[i] = __float2half_rn(xs[i]);
    __half* o = out + (size_t)l * lstride + (size_t)(row_off + r) * (2 * K);
    *(uint4*)(o + k)     = *(uint4*)hi;
    *(uint4*)(o + K + k) = *(uint4*)hi;
}

__global__ void rope_init_kernel() {
    int t = blockIdx.x, j = threadIdx.x;
    double inv   = pow(10000.0, -(2.0 * j) / 64.0);
    double r     = 81920.0 * inv / (2.0 * M_PI);
    double gamma = (r - 1.0) / 31.0;
    gamma = gamma < 0.0 ? 0.0 : (gamma > 1.0 ? 1.0 : gamma);
    double inv2  = inv * ((1.0 - gamma) / 40.0 + gamma);
    double c     = sqrt(0.1 * log(40.0) + 1.0);
    double ang   = (double)t * inv2 / c;
    g_cos[t * 32 + j] = (float)cos(ang);
    g_sin[t * 32 + j] = (float)sin(ang);
}

__global__ void embed_kernel(const int* __restrict__ ids, const float* __restrict__ emb) {
    int t = blockIdx.x;
    const float* src = emb + (size_t)ids[t] * DIM;
    float* dst = g_h + (size_t)t * DIM;
    for (int d = threadIdx.x; d < DIM; d += blockDim.x) dst[d] = src[d];
}

__device__ __forceinline__ float rms_scale(const float* xr, int tid) {
    float s = 0.f;
    #pragma unroll
    for (int i = 0; i < 4; i++) { float v = xr[tid + i * 256]; s += v * v; }
    #pragma unroll
    for (int off = 16; off; off >>= 1) s += __shfl_xor_sync(0xffffffffu, s, off);
    __shared__ float red[8]; __shared__ float rsv;
    if ((tid & 31) == 0) red[tid >> 5] = s;
    __syncthreads();
    if (tid == 0) {
        float t = 0.f;
        #pragma unroll
        for (int i = 0; i < 8; i++) t += red[i];
        rsv = rsqrtf(t / (float)DIM + 1e-6f);
    }
    __syncthreads();
    return rsv;
}

__global__ __launch_bounds__(256) void rmsnorm_expand_kernel(
    const float* __restrict__ x, const float* __restrict__ w, bf16* __restrict__ o) {
    int row = blockIdx.x, tid = threadIdx.x;
    const float* xr = x + (size_t)row * DIM;
    float rs = rms_scale(xr, tid);
    bf16* orow = o + (size_t)row * 3072;
    #pragma unroll
    for (int i = 0; i < 2; i++) {
        int d = 2 * (tid + i * 256);
        float2 xv = *(const float2*)(xr + d);
        float2 wv = *(const float2*)(w + d);
        float y0 = xv.x * rs * wv.x, y1 = xv.y * rs * wv.y;
        bf16 h0, l0, h1, l1;
        split2(y0, h0, l0); split2(y1, h1, l1);
        *(__nv_bfloat162*)(orow + d)        = __nv_bfloat162(h0, h1);
        *(__nv_bfloat162*)(orow + 1024 + d) = __nv_bfloat162(h0, h1);
        *(__nv_bfloat162*)(orow + 2048 + d) = __nv_bfloat162(l0, l1);
    }
}

__global__ __launch_bounds__(256) void rmsnorm_expand_f16_kernel(
    const float* __restrict__ x, const float* __restrict__ w, __half* __restrict__ o) {
    int row = blockIdx.x, tid = threadIdx.x;
    const float* xr = x + (size_t)row * DIM;
    float rs = rms_scale(xr, tid);
    __half* orow = o + (size_t)row * 2048;
    #pragma unroll
    for (int i = 0; i < 2; i++) {
        int d = 2 * (tid + i * 256);
        float2 xv = *(const float2*)(xr + d);
        float2 wv = *(const float2*)(w + d);
        float y0 = xv.x * rs * wv.x, y1 = xv.y * rs * wv.y;
        __half h0, l0, h1, l1;
        split2h(y0, h0, l0); split2h(y1, h1, l1);
        *(__half2*)(orow + d)        = __half2(h0, h1);
        *(__half2*)(orow + 1024 + d) = __half2(l0, l1);
    }
}

// ================= b16 tensor-core GEMM =================
#define BM 128
#define BN 256
#define BKE 64
#define A_BYTES (BM * BKE * 2)
#define B_BYTES (BN * BKE * 2)
#define STAGE_BYTES (A_BYTES + B_BYTES)
#define SMEM_DYN (2 * STAGE_BYTES)

#define CP_ASYNC16(dst, src) \
    asm volatile("cp.async.cg.shared.global [%0], [%1], 16;" :: "r"(dst), "l"(src))
#define CP_COMMIT()  asm volatile("cp.async.commit_group;")
#define CP_WAIT1()   asm volatile("cp.async.wait_group 1;")
#define LDSM_X4(r0, r1, r2, r3, addr) \
    asm volatile("ldmatrix.sync.aligned.m8n8.x4.shared.b16 {%0,%1,%2,%3}, [%4];" \
        : "=r"(r0), "=r"(r1), "=r"(r2), "=r"(r3) : "r"(addr))

template <int FP16>
__device__ __forceinline__ void MMA16(float* c, uint32_t a0, uint32_t a1,
                                      uint32_t a2, uint32_t a3,
                                      uint32_t b0, uint32_t b1) {
    if constexpr (FP16)
        asm volatile("mma.sync.aligned.m16n8k16.row.col.f32.f16.f16.f32 "
            "{%0,%1,%2,%3}, {%4,%5,%6,%7}, {%8,%9}, {%0,%1,%2,%3};"
            : "+f"(c[0]), "+f"(c[1]), "+f"(c[2]), "+f"(c[3])
            : "r"(a0), "r"(a1), "r"(a2), "r"(a3), "r"(b0), "r"(b1));
    else
        asm volatile("mma.sync.aligned.m16n8k16.row.col.f32.bf16.bf16.f32 "
            "{%0,%1,%2,%3}, {%4,%5,%6,%7}, {%8,%9}, {%0,%1,%2,%3};"
            : "+f"(c[0]), "+f"(c[1]), "+f"(c[2]), "+f"(c[3])
            : "r"(a0), "r"(a1), "r"(a2), "r"(a3), "r"(b0), "r"(b1));
}

template <int RES, int FP16>
__global__ __launch_bounds__(256) void gemm_b16(
    const uint16_t* __restrict__ A, const uint16_t* __restrict__ W,
    const float* __restrict__ R, float* __restrict__ C, int N, int K) {
    extern __shared__ __align__(16) char smem[];
    const int tid  = threadIdx.x;
    const int lane = tid & 31;
    const int wid  = tid >> 5;
    const int wm   = wid >> 2;
    const int wn   = wid & 3;
    const int bm   = blockIdx.y * BM;
    const int bn   = blockIdx.x * BN;
    const uint32_t smem_u = (uint32_t)__cvta_generic_to_shared(smem);

    const int lrow = tid >> 3;
    const int lcol = tid & 7;
    const uint16_t* AgBase = A + (size_t)bm * K;
    const uint16_t* WgBase = W + (size_t)bn * K;

    const int flr = lane & 15;
    const int fhi = lane >> 4;
    int aRow[4], aXor[4];
    #pragma unroll
    for (int i = 0; i < 4; i++) { aRow[i] = wm * 64 + i * 16 + flr; aXor[i] = aRow[i] & 7; }
    const int bkf = (lane >> 3) & 1;
    int bRow[4], bXor[4];
    #pragma unroll
    for (int p = 0; p < 4; p++) {
        bRow[p] = wn * 64 + (lane & 7) + fhi * 8 + p * 16;
        bXor[p] = bRow[p] & 7;
    }

    float acc[4][8][4];
    #pragma unroll
    for (int i = 0; i < 4; i++)
        #pragma unroll
        for (int j = 0; j < 8; j++)
            #pragma unroll
            for (int q = 0; q < 4; q++) acc[i][j][q] = 0.f;

    const int nk = K / BKE;
    auto load_stage = [&](int kt) {
        uint32_t base = smem_u + (kt & 1) * STAGE_BYTES;
        int k0 = kt * BKE;
        #pragma unroll
        for (int it = 0; it < 4; it++) {
            int r = lrow + it * 32;
            CP_ASYNC16(base + r * 128 + ((lcol ^ (r & 7)) << 4),
                       AgBase + (size_t)r * K + k0 + lcol * 8);
        }
        uint32_t bb = base + A_BYTES;
        #pragma unroll
        for (int it = 0; it < 8; it++) {
            int r = lrow + it * 32;
            CP_ASYNC16(bb + r * 128 + ((lcol ^ (r & 7)) << 4),
                       WgBase + (size_t)r * K + k0 + lcol * 8);
        }
    };

    load_stage(0);
    CP_COMMIT();
    for (int kt = 0; kt < nk; kt++) {
        if (kt + 1 < nk) load_stage(kt + 1);
        CP_COMMIT();
        CP_WAIT1();
        __syncthreads();
        uint32_t cbase = smem_u + (kt & 1) * STAGE_BYTES;
        #pragma unroll
        for (int s = 0; s < 4; s++) {
            uint32_t af[4][4];
            #pragma unroll
            for (int i = 0; i < 4; i++)
                LDSM_X4(af[i][0], af[i][1], af[i][2], af[i][3],
                        cbase + aRow[i] * 128 + (((2 * s + fhi) ^ aXor[i]) << 4));
            #pragma unroll
            for (int p = 0; p < 4; p++) {
                uint32_t b0, b1, b2, b3;
                LDSM_X4(b0, b1, b2, b3,
                        cbase + (uint32_t)A_BYTES + bRow[p] * 128 + (((2 * s + bkf) ^ bXor[p]) << 4));
                #pragma unroll
                for (int i = 0; i < 4; i++) {
                    MMA16<FP16>(acc[i][2 * p],     af[i][0], af[i][1], af[i][2], af[i][3], b0, b1);
                    MMA16<FP16>(acc[i][2 * p + 1], af[i][0], af[i][1], af[i][2], af[i][3], b2, b3);
                }
            }
        }
        __syncthreads();
    }

    const int gid = lane >> 2, tig = lane & 3;
    #pragma unroll
    for (int i = 0; i < 4; i++) {
        int r0 = bm + wm * 64 + i * 16 + gid;
        #pragma unroll
        for (int j = 0; j < 8; j++) {
            int c0 = bn + wn * 64 + j * 8 + tig * 2;
            size_t o0 = (size_t)r0 * N + c0;
            size_t o1 = o0 + (size_t)8 * N;
            float2 v0 = make_float2(acc[i][j][0], acc[i][j][1]);
            float2 v1 = make_float2(acc[i][j][2], acc[i][j][3]);
            if (RES) {
                float2 ra = *(const float2*)(R + o0);
                float2 rb = *(const float2*)(R + o1);
                v0.x += ra.x; v0.y += ra.y; v1.x += rb.x; v1.y += rb.y;
            }
            *(float2*)(C + o0) = v0;
            *(float2*)(C + o1) = v1;
        }
    }
}

__global__ void rope_kernel(float* __restrict__ x, int nheads, int off) {
    int idx = blockIdx.x * 256 + threadIdx.x;
    int i  = idx & 31;
    int hh = (idx >> 5) % nheads;
    int t  = idx / (32 * nheads);
    int s  = t & (SEQ - 1);
    float c  = g_cos[s * 32 + i];
    float sn = g_sin[s * 32 + i];
    float* p = x + (size_t)t * 1536 + off + hh * HDIM;
    float x1 = p[i], x2 = p[i + 32];
    p[i]      = x1 * c - x2 * sn;
    p[i + 32] = x2 * c + x1 * sn;
}

// ---- attention operand expansion (post-rope) ----
__global__ void qexp_kernel(const float* __restrict__ qkv) {
    int idx = blockIdx.x * 256 + threadIdx.x;
    int d = idx & 63, t = (idx >> 6) & 2047, h = (idx >> 17) & 15, b = idx >> 21;
    float v = qkv[(size_t)(b * 2048 + t) * 1536 + h * 64 + d] * 0.125f;
    bf16 hi, lo; split2(v, hi, lo);
    g_qhi[idx] = hi; g_qlo[idx] = lo;
}
__global__ void kexp_kernel(const float* __restrict__ qkv) {
    int idx = blockIdx.x * 256 + threadIdx.x;
    int d = idx & 63, t = (idx >> 6) & 2047, g = (idx >> 17) & 3, b = idx >> 19;
    float v = qkv[(size_t)(b * 2048 + t) * 1536 + 1024 + g * 64 + d];
    bf16 hi, lo; split2(v, hi, lo);
    g_khi[idx] = hi; g_klo[idx] = lo;
}
__global__ __launch_bounds__(256) void vexp_kernel(const float* __restrict__ qkv) {
    __shared__ bf16 shi[64][65], slo[64][65];
    int bgj = blockIdx.x;
    int jt = bgj & 31, bg = bgj >> 5;
    int g = bg & 3, b = bg >> 2;
    int tid = threadIdx.x;
    #pragma unroll
    for (int i = 0; i < 16; i++) {
        int e = tid + i * 256; int tt = e >> 6, d = e & 63;
        float v = qkv[(size_t)(b * 2048 + jt * 64 + tt) * 1536 + 1280 + g * 64 + d];
        split2(v, shi[tt][d], slo[tt][d]);
    }
    __syncthreads();
    size_t ob = (size_t)bgj * 4096;
    #pragma unroll
    for (int i = 0; i < 16; i++) {
        int e = tid + i * 256; int d = e >> 6, tt = e & 63;
        g_vthi[ob + e] = shi[tt][d];
        g_vtlo[ob + e] = slo[tt][d];
    }
}

// ---- tensor-core causal flash attention (128 thr = 4 warps x 16 q) ----
#define ATT_SMEM (16384 + 2 * 32768)   // Q(hi+lo) + 2 stages x (Khi|Klo|VThi|VTlo)
__global__ __launch_bounds__(128) void attn_fa(bf16* __restrict__ oe) {
    extern __shared__ __align__(16) char sm[];
    const uint32_t su = (uint32_t)__cvta_generic_to_shared(sm);
    const uint32_t qhi_s = su, qlo_s = su + 8192;

    const int qt = blockIdx.x, h = blockIdx.y, b = blockIdx.z;
    const int g = h >> 2;
    const int tid = threadIdx.x, lane = tid & 31, w = tid >> 5;
    const int flr = lane & 15, fhi = lane >> 4, bk = (lane >> 3) & 1;
    const int gid = lane >> 2, tig = lane & 3;
    const int aRow = w * 16 + flr, aXor = aRow & 7;
    int bRow[4], bXor[4];
    #pragma unroll
    for (int p = 0; p < 4; p++) { bRow[p] = (lane & 7) + fhi * 8 + p * 16; bXor[p] = bRow[p] & 7; }

    const bf16* qh = g_qhi + ((size_t)(b * 16 + h) * 2048 + qt * 64) * 64;
    const bf16* ql = g_qlo + ((size_t)(b * 16 + h) * 2048 + qt * 64) * 64;
    #pragma unroll
    for (int i = 0; i < 4; i++) {
        int gd = tid + i * 128, r = gd >> 3, c = gd & 7;
        uint32_t off = r * 128 + ((c ^ (r & 7)) << 4);
        CP_ASYNC16(qhi_s + off, qh + (size_t)r * 64 + c * 8);
        CP_ASYNC16(qlo_s + off, ql + (size_t)r * 64 + c * 8);
    }
    auto loadKV = [&](int j, int st) {
        uint32_t base = su + 16384 + st * 32768;
        const bf16* kh = g_khi + ((size_t)(b * 4 + g) * 2048 + j * 64) * 64;
        const bf16* kl = g_klo + ((size_t)(b * 4 + g) * 2048 + j * 64) * 64;
        const bf16* vh = g_vthi + (size_t)((b * 4 + g) * 32 + j) * 4096;
        const bf16* vl = g_vtlo + (size_t)((b * 4 + g) * 32 + j) * 4096;
        #pragma unroll
        for (int i = 0; i < 4; i++) {
            int gd = tid + i * 128, r = gd >> 3, c = gd & 7;
            uint32_t off = r * 128 + ((c ^ (r & 7)) << 4);
            CP_ASYNC16(base + off,         kh + (size_t)r * 64 + c * 8);
            CP_ASYNC16(base + 8192 + off,  kl + (size_t)r * 64 + c * 8);
            CP_ASYNC16(base + 16384 + off, vh + (size_t)r * 64 + c * 8);
            CP_ASYNC16(base + 24576 + off, vl + (size_t)r * 64 + c * 8);
        }
    };
    loadKV(0, 0);
    CP_COMMIT();

    float m0 = -1e30f, m1 = -1e30f, l0 = 0.f, l1 = 0.f;
    float oacc[8][4];
    #pragma unroll
    for (int j = 0; j < 8; j++)
        #pragma unroll
        for (int q = 0; q < 4; q++) oacc[j][q] = 0.f;
    const int qr0 = qt * 64 + w * 16 + gid;

    for (int j = 0; j <= qt; j++) {
        __syncthreads();
        if (j + 1 <= qt) loadKV(j + 1, (j + 1) & 1);
        CP_COMMIT();
        CP_WAIT1();
        __syncthreads();
        const uint32_t kb = su + 16384 + (j & 1) * 32768;

        // QK^T, 3-term bf16 split
        float sacc[8][4];
        #pragma unroll
        for (int jn = 0; jn < 8; jn++)
            #pragma unroll
            for (int q = 0; q < 4; q++) sacc[jn][q] = 0.f;
        #pragma unroll
        for (int term = 0; term < 3; term++) {
            uint32_t ab = (term == 2) ? qlo_s : qhi_s;
            uint32_t bb = kb + ((term == 1) ? 8192 : 0);
            #pragma unroll
            for (int s = 0; s < 4; s++) {
                uint32_t a0, a1, a2, a3;
                LDSM_X4(a0, a1, a2, a3, ab + aRow * 128 + (((2 * s + fhi) ^ aXor) << 4));
                #pragma unroll
                for (int p = 0; p < 4; p++) {
                    uint32_t b0, b1, b2, b3;
                    LDSM_X4(b0, b1, b2, b3,
                            bb + bRow[p] * 128 + (((2 * s + bk) ^ bXor[p]) << 4));
                    MMA16<0>(sacc[2 * p],     a0, a1, a2, a3, b0, b1);
                    MMA16<0>(sacc[2 * p + 1], a0, a1, a2, a3, b2, b3);
                }
            }
        }

        if (j == qt) {   // causal mask on diagonal tile
            #pragma unroll
            for (int jn = 0; jn < 8; jn++) {
                int c0 = j * 64 + jn * 8 + tig * 2;
                if (c0     > qr0)     sacc[jn][0] = -1e30f;
                if (c0 + 1 > qr0)     sacc[jn][1] = -1e30f;
                if (c0     > qr0 + 8) sacc[jn][2] = -1e30f;
                if (c0 + 1 > qr0 + 8) sacc[jn][3] = -1e30f;
            }
        }

        float t0 = -1e30f, t1 = -1e30f;
        #pragma unroll
        for (int jn = 0; jn < 8; jn++) {
            t0 = fmaxf(t0, fmaxf(sacc[jn][0], sacc[jn][1]));
            t1 = fmaxf(t1, fmaxf(sacc[jn][2], sacc[jn][3]));
        }
        t0 = fmaxf(t0, __shfl_xor_sync(0xffffffffu, t0, 1));
        t0 = fmaxf(t0, __shfl_xor_sync(0xffffffffu, t0, 2));
        t1 = fmaxf(t1, __shfl_xor_sync(0xffffffffu, t1, 1));
        t1 = fmaxf(t1, __shfl_xor_sync(0xffffffffu, t1, 2));
        float nm0 = fmaxf(m0, t0), nm1 = fmaxf(m1, t1);
        float cr0 = __expf(m0 - nm0), cr1 = __expf(m1 - nm1);
        l0 *= cr0; l1 *= cr1;
        #pragma unroll
        for (int jn = 0; jn < 8; jn++) {
            oacc[jn][0] *= cr0; oacc[jn][1] *= cr0;
            oacc[jn][2] *= cr1; oacc[jn][3] *= cr1;
        }

        // P = exp(s-m); build PV A-fragments via C->A layout identity
        uint32_t aP[4][4], aL[4][4];
        float s0 = 0.f, s1 = 0.f;
        #pragma unroll
        for (int jn = 0; jn < 8; jn++) {
            float p0 = __expf(sacc[jn][0] - nm0), p1 = __expf(sacc[jn][1] - nm0);
            float p2 = __expf(sacc[jn][2] - nm1), p3 = __expf(sacc[jn][3] - nm1);
            s0 += p0 + p1; s1 += p2 + p3;
            bf16 h0, e0, h1, e1, h2, e2, h3, e3;
            split2(p0, h0, e0); split2(p1, h1, e1);
            split2(p2, h2, e2); split2(p3, h3, e3);
            int sp = jn >> 1, wh = jn & 1;
            aP[sp][2 * wh]     = pack_bf2(h0, h1);
            aP[sp][2 * wh + 1] = pack_bf2(h2, h3);
            aL[sp][2 * wh]     = pack_bf2(e0, e1);
            aL[sp][2 * wh + 1] = pack_bf2(e2, e3);
        }
        s0 += __shfl_xor_sync(0xffffffffu, s0, 1);
        s0 += __shfl_xor_sync(0xffffffffu, s0, 2);
        s1 += __shfl_xor_sync(0xffffffffu, s1, 1);
        s1 += __shfl_xor_sync(0xffffffffu, s1, 2);
        l0 += s0; l1 += s1;
        m0 = nm0; m1 = nm1;

        // P x V: phi*vhi + phi*vlo + plo*vhi (VT tiles)
        #pragma unroll
        for (int term = 0; term < 3; term++) {
            uint32_t vb = kb + 16384 + ((term == 1) ? 8192 : 0);
            #pragma unroll
            for (int s = 0; s < 4; s++) {
                uint32_t A0 = (term == 2) ? aL[s][0] : aP[s][0];
                uint32_t A1 = (term == 2) ? aL[s][1] : aP[s][1];
                uint32_t A2 = (term == 2) ? aL[s][2] : aP[s][2];
                uint32_t A3 = (term == 2) ? aL[s][3] : aP[s][3];
                #pragma unroll
                for (int p = 0; p < 4; p++) {
                    uint32_t b0, b1, b2, b3;
                    LDSM_X4(b0, b1, b2, b3,
                            vb + bRow[p] * 128 + (((2 * s + bk) ^ bXor[p]) << 4));
                    MMA16<0>(oacc[2 * p],     A0, A1, A2, A3, b0, b1);
                    MMA16<0>(oacc[2 * p + 1], A0, A1, A2, A3, b2, b3);
                }
            }
        }
    }

    float i0 = 1.f / l0, i1 = 1.f / l1;
    bf16* op0 = oe + (size_t)(b * SEQ + qt * 64 + w * 16 + gid) * 3072 + h * 64;
    bf16* op1 = op0 + (size_t)8 * 3072;
    #pragma unroll
    for (int jn = 0; jn < 8; jn++) {
        int c = jn * 8 + tig * 2;
        bf16 h0, e0, h1, e1;
        split2(oacc[jn][0] * i0, h0, e0); split2(oacc[jn][1] * i0, h1, e1);
        *(__nv_bfloat162*)(op0 + c)        = __nv_bfloat162(h0, h1);
        *(__nv_bfloat162*)(op0 + 1024 + c) = __nv_bfloat162(h0, h1);
        *(__nv_bfloat162*)(op0 + 2048 + c) = __nv_bfloat162(e0, e1);
        split2(oacc[jn][2] * i1, h0, e0); split2(oacc[jn][3] * i1, h1, e1);
        *(__nv_bfloat162*)(op1 + c)        = __nv_bfloat162(h0, h1);
        *(__nv_bfloat162*)(op1 + 1024 + c) = __nv_bfloat162(h0, h1);
        *(__nv_bfloat162*)(op1 + 2048 + c) = __nv_bfloat162(e0, e1);
    }
}

__global__ void swiglu_expand_f16_kernel() {
    int i4 = (blockIdx.x * 256 + threadIdx.x) * 4;
    int t = i4 >> 12, c = i4 & 4095;
    float4 a4 = *(const float4*)(g_f13 + (size_t)t * 8192 + c);
    float4 b4 = *(const float4*)(g_f13 + (size_t)t * 8192 + 4096 + c);
    float as[4] = {a4.x, a4.y, a4.z, a4.w};
    float bs[4] = {b4.x, b4.y, b4.z, b4.w};
    __half hi[4], lo[4];
    #pragma unroll
    for (int i = 0; i < 4; i++) {
        float u = (as[i] / (1.f + __expf(-as[i]))) * bs[i];
        split2h(u, hi[i], lo[i]);
    }
    __half* o = g_f1h + (size_t)t * 8192;
    *(uint2*)(o + c)        = *(uint2*)hi;
    *(uint2*)(o + 4096 + c) = *(uint2*)lo;
}

extern "C" void kernel_launch(void* const* d_in, const int* in_sizes, int n_in,
                              void* d_out, int out_size) {
    const int*   ids = (const int*)d_in[0];
    const float* emb = (const float*)d_in[1];
    const float* wq  = (const float*)d_in[2];
    const float* wk  = (const float*)d_in[3];
    const float* wv  = (const float*)d_in[4];
    const float* wo  = (const float*)d_in[5];
    const float* n1  = (const float*)d_in[6];
    const float* n2  = (const float*)d_in[7];
    const float* w1  = (const float*)d_in[8];
    const float* w2  = (const float*)d_in[9];
    const float* w3  = (const float*)d_in[10];
    const float* fnw = (const float*)d_in[11];
    float* out = (float*)d_out;

    static int smem_set = 0;
    if (!smem_set) {
        cudaFuncSetAttribute(gemm_b16<0,0>, cudaFuncAttributeMaxDynamicSharedMemorySize, SMEM_DYN);
        cudaFuncSetAttribute(gemm_b16<1,0>, cudaFuncAttributeMaxDynamicSharedMemorySize, SMEM_DYN);
        cudaFuncSetAttribute(gemm_b16<0,1>, cudaFuncAttributeMaxDynamicSharedMemorySize, SMEM_DYN);
        cudaFuncSetAttribute(gemm_b16<1,1>, cudaFuncAttributeMaxDynamicSharedMemorySize, SMEM_DYN);
        cudaFuncSetAttribute(attn_fa,       cudaFuncAttributeMaxDynamicSharedMemorySize, ATT_SMEM);
        smem_set = 1;
    }

    float *h, *qkv, *f13;
    bf16 *xne, *atte, *ewqkv, *ewo;
    __half *xnh, *f1h, *ew13h, *ew2h, *eembh;
    cudaGetSymbolAddress((void**)&h,     g_h);
    cudaGetSymbolAddress((void**)&qkv,   g_qkv);
    cudaGetSymbolAddress((void**)&f13,   g_f13);
    cudaGetSymbolAddress((void**)&xne,   g_xne);
    cudaGetSymbolAddress((void**)&atte,  g_atte);
    cudaGetSymbolAddress((void**)&xnh,   g_xnh);
    cudaGetSymbolAddress((void**)&f1h,   g_f1h);
    cudaGetSymbolAddress((void**)&ewqkv, e_wqkv);
    cudaGetSymbolAddress((void**)&ewo,   e_wo);
    cudaGetSymbolAddress((void**)&ew13h, e_w13h);
    cudaGetSymbolAddress((void**)&ew2h,  e_w2h);
    cudaGetSymbolAddress((void**)&eembh, e_embh);

    expand_w_kernel<<<(NLAYER * 1024 * 1024) / 2048, 256>>>(wq, ewqkv, 1024, 1024, (size_t)1536 * 3072, 0);
    expand_w_kernel<<<(NLAYER * 256  * 1024) / 2048, 256>>>(wk, ewqkv, 1024, 256,  (size_t)1536 * 3072, 1024);
    expand_w_kernel<<<(NLAYER * 256  * 1024) / 2048, 256>>>(wv, ewqkv, 1024, 256,  (size_t)1536 * 3072, 1280);
    expand_w_kernel<<<(NLAYER * 1024 * 1024) / 2048, 256>>>(wo, ewo,   1024, 1024, (size_t)1024 * 3072, 0);
    expand_w_f16_kernel<<<(NLAYER * 4096 * 1024) / 2048, 256>>>(w1, ew13h, 1024, 4096, (size_t)8192 * 2048, 0);
    expand_w_f16_kernel<<<(NLAYER * 4096 * 1024) / 2048, 256>>>(w3, ew13h, 1024, 4096, (size_t)8192 * 2048, 4096);
    expand_w_f16_kernel<<<(NLAYER * 1024 * 4096) / 2048, 256>>>(w2, ew2h,  4096, 1024, (size_t)1024 * 8192, 0);
    expand_w_f16_kernel<<<(VOCAB * 1024) / 2048, 256>>>(emb, eembh, 1024, VOCAB, 0, 0);

    rope_init_kernel<<<SEQ, 32>>>();
    embed_kernel<<<TOK, 256>>>(ids, emb);

    for (int l = 0; l < NLAYER; l++) {
        rmsnorm_expand_kernel<<<TOK, 256>>>(h, n1 + (size_t)l * DIM, xne);
        gemm_b16<0,0><<<dim3(1536 / BN, TOK / BM), 256, SMEM_DYN>>>(
            (const uint16_t*)xne, (const uint16_t*)(ewqkv + (size_t)l * 1536 * 3072),
            nullptr, qkv, 1536, 3072);
        rope_kernel<<<(TOK * NHEAD * 32) / 256, 256>>>(qkv, NHEAD, 0);
        rope_kernel<<<(TOK * KVHEAD * 32) / 256, 256>>>(qkv, KVHEAD, 1024);
        qexp_kernel<<<(BATCH * NHEAD * SEQ * 64) / 256, 256>>>(qkv);
        kexp_kernel<<<(BATCH * KVHEAD * SEQ * 64) / 256, 256>>>(qkv);
        vexp_kernel<<<BATCH * KVHEAD * 32, 256>>>(qkv);
        attn_fa<<<dim3(SEQ / 64, NHEAD, BATCH), 128, ATT_SMEM>>>(atte);
        gemm_b16<1,0><<<dim3(1024 / BN, TOK / BM), 256, SMEM_DYN>>>(
            (const uint16_t*)atte, (const uint16_t*)(ewo + (size_t)l * 1024 * 3072),
            h, h, 1024, 3072);
        rmsnorm_expand_f16_kernel<<<TOK, 256>>>(h, n2 + (size_t)l * DIM, xnh);
        gemm_b16<0,1><<<dim3(8192 / BN, TOK / BM), 256, SMEM_DYN>>>(
            (const uint16_t*)xnh, (const uint16_t*)(ew13h + (size_t)l * 8192 * 2048),
            nullptr, f13, 8192, 2048);
        swiglu_expand_f16_kernel<<<(TOK * FF) / 1024, 256>>>();
        gemm_b16<1,1><<<dim3(1024 / BN, TOK / BM), 256, SMEM_DYN>>>(
            (const uint16_t*)f1h, (const uint16_t*)(ew2h + (size_t)l * 1024 * 8192),
            h, h, 1024, 8192);
    }
    rmsnorm_expand_f16_kernel<<<TOK, 256>>>(h, fnw, xnh);
    gemm_b16<0,1><<<dim3(VOCAB / BN, TOK / BM), 256, SMEM_DYN>>>(
        (const uint16_t*)xnh, (const uint16_t*)eembh, nullptr, out, VOCAB, 2048);
}